// round 1
// baseline (speedup 1.0000x reference)
#include <cuda_runtime.h>
#include <cstdint>

#define NB       4
#define NN       2048
#define DMODEL   1024
#define GEOM     32
#define KH       16          // GEOM/2 (f32x2-packed)
#define CLAMP_V  10.0f

typedef unsigned long long ull;

// Scratch for G = H @ W^T, [NB*NN, GEOM] floats = 1 MB (device global: no allocs allowed)
__device__ __align__(16) float g_G[NB * NN * GEOM];

// ---------------- packed f32x2 helpers (sm_10x FFMA2 via PTX) ----------------
__device__ __forceinline__ ull ffma2(ull a, ull b, ull c) {
    ull d;
    asm("fma.rn.f32x2 %0, %1, %2, %3;" : "=l"(d) : "l"(a), "l"(b), "l"(c));
    return d;
}
__device__ __forceinline__ ull pack2(float x, float y) {
    ull r;
    asm("mov.b64 %0, {%1, %2};" : "=l"(r) : "f"(x), "f"(y));
    return r;
}
__device__ __forceinline__ float2 unpack2(ull v) {
    float2 f;
    asm("mov.b64 {%0, %1}, %2;" : "=f"(f.x), "=f"(f.y) : "l"(v));
    return f;
}

// ============================================================================
// Kernel 1: G[n][k] = sum_d H[n][d] * W[k][d]
// 128 blocks x 256 threads; each block: 64 rows x 32 k, D chunked by 64.
// Register double-buffering of global loads; packed FFMA2 over d.
// ============================================================================
#define TN1 64

__global__ __launch_bounds__(256)
void geom_proj_kernel(const float* __restrict__ H, const float* __restrict__ W) {
    __shared__ ull Hs[TN1][34];   // [row][d-pair], pad for 16B-aligned stores
    __shared__ ull WsT[32][33];   // [d-pair][k] transposed: main reads conflict-free

    const int tid = threadIdx.x;
    const int tx  = tid & 31;     // k
    const int ty  = tid >> 5;     // row group (0..7)
    const int n0  = blockIdx.x * TN1;

    const float4* __restrict__ H4 = (const float4*)H;
    const float4* __restrict__ W4 = (const float4*)W;

    float4 hreg[4];
    float4 wreg[2];

    // stage chunk 0
    #pragma unroll
    for (int p = 0; p < 4; p++) {
        int idx = tid + 256 * p;
        int row = idx >> 4, fc = idx & 15;
        hreg[p] = H4[(size_t)(n0 + row) * 256 + fc];
    }
    #pragma unroll
    for (int p = 0; p < 2; p++) {
        int idx = tid + 256 * p;
        int k = idx >> 4, fc = idx & 15;
        wreg[p] = W4[k * 256 + fc];
    }

    ull acc[8];
    #pragma unroll
    for (int r = 0; r < 8; r++) acc[r] = 0ULL;

    for (int c = 0; c < 16; c++) {
        __syncthreads();
        #pragma unroll
        for (int p = 0; p < 4; p++) {
            int idx = tid + 256 * p;
            int row = idx >> 4, fc = idx & 15;
            Hs[row][2 * fc]     = pack2(hreg[p].x, hreg[p].y);
            Hs[row][2 * fc + 1] = pack2(hreg[p].z, hreg[p].w);
        }
        #pragma unroll
        for (int p = 0; p < 2; p++) {
            int idx = tid + 256 * p;
            int k = idx >> 4, fc = idx & 15;
            WsT[2 * fc][k]     = pack2(wreg[p].x, wreg[p].y);
            WsT[2 * fc + 1][k] = pack2(wreg[p].z, wreg[p].w);
        }
        __syncthreads();

        if (c < 15) {   // prefetch next chunk behind compute
            #pragma unroll
            for (int p = 0; p < 4; p++) {
                int idx = tid + 256 * p;
                int row = idx >> 4, fc = idx & 15;
                hreg[p] = H4[(size_t)(n0 + row) * 256 + (c + 1) * 16 + fc];
            }
            #pragma unroll
            for (int p = 0; p < 2; p++) {
                int idx = tid + 256 * p;
                int k = idx >> 4, fc = idx & 15;
                wreg[p] = W4[k * 256 + (c + 1) * 16 + fc];
            }
        }

        #pragma unroll
        for (int dc = 0; dc < 32; dc++) {
            ull wv = WsT[dc][tx];
            #pragma unroll
            for (int r = 0; r < 8; r++)
                acc[r] = ffma2(Hs[ty * 8 + r][dc], wv, acc[r]);
        }
    }

    #pragma unroll
    for (int r = 0; r < 8; r++) {
        float2 v = unpack2(acc[r]);
        g_G[(size_t)(n0 + ty * 8 + r) * GEOM + tx] = v.x + v.y;
    }
}

// ============================================================================
// Kernel 2: out[b,i,j] = clamp(alpha*Bprev - beta*max(0, Gsq_i+Gsq_j-2*G_i.G_j))
// Grid (32,32,4), 256 threads, 64x64 tile, 4x4 register micro-tile (strided
// i/j mapping -> conflict-free smem reads and fully coalesced gmem).
// ============================================================================
__global__ __launch_bounds__(256)
void bias_update_kernel(const float* __restrict__ Bprev,
                        const float* __restrict__ alpha_p,
                        const float* __restrict__ beta_p,
                        float* __restrict__ Out) {
    __shared__ ull GiT[16][65];   // [kpair][i], padded: conflict-free transposed fills
    __shared__ ull GjT[16][65];   // [kpair][j]
    __shared__ float GsqI[64];
    __shared__ float GsqJ[64];

    const int tid = threadIdx.x;
    const int tx  = tid & 15;
    const int ty  = tid >> 4;
    const int b   = blockIdx.z;
    const int i0  = blockIdx.y * 64;
    const int j0  = blockIdx.x * 64;

    const ull* __restrict__ G2 = (const ull*)g_G;
    const size_t gbase = (size_t)b * NN * KH;     // u64 units
    const size_t obase = (size_t)b * NN * NN;

    // Issue all global loads up front for MLP.
    ull gi[4], gj[4];
    #pragma unroll
    for (int p = 0; p < 4; p++) {
        int idx = tid + 256 * p;
        int nl = idx >> 4, kk = idx & 15;
        gi[p] = G2[gbase + (size_t)(i0 + nl) * KH + kk];
        gj[p] = G2[gbase + (size_t)(j0 + nl) * KH + kk];
    }

    const float alpha = __ldg(alpha_p);
    const float beta  = __ldg(beta_p);

    float bp[4][4];
    #pragma unroll
    for (int ii = 0; ii < 4; ii++) {
        const size_t rb = obase + (size_t)(i0 + ty + 16 * ii) * NN + j0;
        #pragma unroll
        for (int jj = 0; jj < 4; jj++)
            bp[ii][jj] = __ldg(&Bprev[rb + tx + 16 * jj]);
    }

    #pragma unroll
    for (int p = 0; p < 4; p++) {
        int idx = tid + 256 * p;
        int nl = idx >> 4, kk = idx & 15;
        GiT[kk][nl] = gi[p];
        GjT[kk][nl] = gj[p];
    }
    __syncthreads();

    // Row squared-norms from the resident tiles (threads 0..127)
    if (tid < 128) {
        const int nl = tid & 63;
        float s = 0.f;
        if (tid < 64) {
            #pragma unroll
            for (int kk = 0; kk < 16; kk++) {
                float2 v = unpack2(GiT[kk][nl]);
                s += v.x * v.x + v.y * v.y;
            }
            GsqI[nl] = s;
        } else {
            #pragma unroll
            for (int kk = 0; kk < 16; kk++) {
                float2 v = unpack2(GjT[kk][nl]);
                s += v.x * v.x + v.y * v.y;
            }
            GsqJ[nl] = s;
        }
    }
    __syncthreads();

    ull acc[4][4];
    #pragma unroll
    for (int ii = 0; ii < 4; ii++)
        #pragma unroll
        for (int jj = 0; jj < 4; jj++) acc[ii][jj] = 0ULL;

    #pragma unroll
    for (int kk = 0; kk < 16; kk++) {
        ull av[4], bv[4];
        #pragma unroll
        for (int ii = 0; ii < 4; ii++) av[ii] = GiT[kk][ty + 16 * ii];
        #pragma unroll
        for (int jj = 0; jj < 4; jj++) bv[jj] = GjT[kk][tx + 16 * jj];
        #pragma unroll
        for (int ii = 0; ii < 4; ii++)
            #pragma unroll
            for (int jj = 0; jj < 4; jj++)
                acc[ii][jj] = ffma2(av[ii], bv[jj], acc[ii][jj]);
    }

    #pragma unroll
    for (int ii = 0; ii < 4; ii++) {
        const float si = GsqI[ty + 16 * ii];
        const size_t rb = obase + (size_t)(i0 + ty + 16 * ii) * NN + j0;
        #pragma unroll
        for (int jj = 0; jj < 4; jj++) {
            float2 v = unpack2(acc[ii][jj]);
            float dist = si + GsqJ[tx + 16 * jj] - 2.0f * (v.x + v.y);
            dist = fmaxf(dist, 0.0f);
            float o = alpha * bp[ii][jj] - beta * dist;
            o = fminf(fmaxf(o, -CLAMP_V), CLAMP_V);
            Out[rb + tx + 16 * jj] = o;
        }
    }
}

// ============================================================================
extern "C" void kernel_launch(void* const* d_in, const int* in_sizes, int n_in,
                              void* d_out, int out_size) {
    const float* H     = (const float*)d_in[0];   // [4,2048,1024]
    const float* Bprev = (const float*)d_in[1];   // [4,2048,2048]
    const float* W     = (const float*)d_in[2];   // [32,1024]
    const float* alpha = (const float*)d_in[3];   // scalar
    const float* beta  = (const float*)d_in[4];   // scalar
    float* Out = (float*)d_out;

    geom_proj_kernel<<<(NB * NN) / TN1, 256>>>(H, W);
    bias_update_kernel<<<dim3(NN / 64, NN / 64, NB), 256>>>(Bprev, alpha, beta, Out);
}

// round 2
// speedup vs baseline: 1.0083x; 1.0083x over previous
#include <cuda_runtime.h>
#include <cstdint>

#define NB       4
#define NN       2048
#define DMODEL   1024
#define GEOM     32
#define KH       16          // GEOM/2 (f32x2-packed)
#define CLAMP_V  10.0f

typedef unsigned long long ull;

// Scratch for G = H @ W^T, [NB*NN, GEOM] floats = 1 MB (device global: no allocs allowed)
__device__ __align__(16) float g_G[NB * NN * GEOM];

// ---------------- packed f32x2 helpers (sm_10x FFMA2 via PTX) ----------------
__device__ __forceinline__ ull ffma2(ull a, ull b, ull c) {
    ull d;
    asm("fma.rn.f32x2 %0, %1, %2, %3;" : "=l"(d) : "l"(a), "l"(b), "l"(c));
    return d;
}
__device__ __forceinline__ ull pack2(float x, float y) {
    ull r;
    asm("mov.b64 %0, {%1, %2};" : "=l"(r) : "f"(x), "f"(y));
    return r;
}
__device__ __forceinline__ float2 unpack2(ull v) {
    float2 f;
    asm("mov.b64 {%0, %1}, %2;" : "=f"(f.x), "=f"(f.y) : "l"(v));
    return f;
}

// ============================================================================
// Kernel 1: G[n][k] = sum_d H[n][d] * W[k][d]
// 128 blocks x 256 threads; each block: 64 rows x 32 k, D chunked by 64.
// Register double-buffering of global loads; packed FFMA2 over d.
// ============================================================================
#define TN1 64

__global__ __launch_bounds__(256)
void geom_proj_kernel(const float* __restrict__ H, const float* __restrict__ W) {
    __shared__ ull Hs[TN1][34];   // [row][d-pair], pad for 16B-aligned stores
    __shared__ ull WsT[32][33];   // [d-pair][k] transposed: main reads conflict-free

    const int tid = threadIdx.x;
    const int tx  = tid & 31;     // k
    const int ty  = tid >> 5;     // row group (0..7)
    const int n0  = blockIdx.x * TN1;

    const float4* __restrict__ H4 = (const float4*)H;
    const float4* __restrict__ W4 = (const float4*)W;

    float4 hreg[4];
    float4 wreg[2];

    // stage chunk 0
    #pragma unroll
    for (int p = 0; p < 4; p++) {
        int idx = tid + 256 * p;
        int row = idx >> 4, fc = idx & 15;
        hreg[p] = H4[(size_t)(n0 + row) * 256 + fc];
    }
    #pragma unroll
    for (int p = 0; p < 2; p++) {
        int idx = tid + 256 * p;
        int k = idx >> 4, fc = idx & 15;
        wreg[p] = W4[k * 256 + fc];
    }

    ull acc[8];
    #pragma unroll
    for (int r = 0; r < 8; r++) acc[r] = 0ULL;

    for (int c = 0; c < 16; c++) {
        __syncthreads();
        #pragma unroll
        for (int p = 0; p < 4; p++) {
            int idx = tid + 256 * p;
            int row = idx >> 4, fc = idx & 15;
            Hs[row][2 * fc]     = pack2(hreg[p].x, hreg[p].y);
            Hs[row][2 * fc + 1] = pack2(hreg[p].z, hreg[p].w);
        }
        #pragma unroll
        for (int p = 0; p < 2; p++) {
            int idx = tid + 256 * p;
            int k = idx >> 4, fc = idx & 15;
            WsT[2 * fc][k]     = pack2(wreg[p].x, wreg[p].y);
            WsT[2 * fc + 1][k] = pack2(wreg[p].z, wreg[p].w);
        }
        __syncthreads();

        if (c < 15) {   // prefetch next chunk behind compute
            #pragma unroll
            for (int p = 0; p < 4; p++) {
                int idx = tid + 256 * p;
                int row = idx >> 4, fc = idx & 15;
                hreg[p] = H4[(size_t)(n0 + row) * 256 + (c + 1) * 16 + fc];
            }
            #pragma unroll
            for (int p = 0; p < 2; p++) {
                int idx = tid + 256 * p;
                int k = idx >> 4, fc = idx & 15;
                wreg[p] = W4[k * 256 + (c + 1) * 16 + fc];
            }
        }

        #pragma unroll
        for (int dc = 0; dc < 32; dc++) {
            ull wv = WsT[dc][tx];
            #pragma unroll
            for (int r = 0; r < 8; r++)
                acc[r] = ffma2(Hs[ty * 8 + r][dc], wv, acc[r]);
        }
    }

    #pragma unroll
    for (int r = 0; r < 8; r++) {
        float2 v = unpack2(acc[r]);
        g_G[(size_t)(n0 + ty * 8 + r) * GEOM + tx] = v.x + v.y;
    }
}

// ============================================================================
// Kernel 2: out[b,i,j] = clamp(alpha*Bprev - beta*max(0, Gsq_i+Gsq_j-2*G_i.G_j))
// Grid (32,32,4), 256 threads, 64x64 tile, 4x4 register micro-tile (strided
// i/j mapping -> conflict-free smem reads and fully coalesced gmem).
// ============================================================================
__global__ __launch_bounds__(256)
void bias_update_kernel(const float* __restrict__ Bprev,
                        const float* __restrict__ alpha_p,
                        const float* __restrict__ beta_p,
                        float* __restrict__ Out) {
    __shared__ ull GiT[16][65];   // [kpair][i], padded: conflict-free transposed fills
    __shared__ ull GjT[16][65];   // [kpair][j]
    __shared__ float GsqI[64];
    __shared__ float GsqJ[64];

    const int tid = threadIdx.x;
    const int tx  = tid & 15;
    const int ty  = tid >> 4;
    const int b   = blockIdx.z;
    const int i0  = blockIdx.y * 64;
    const int j0  = blockIdx.x * 64;

    const ull* __restrict__ G2 = (const ull*)g_G;
    const size_t gbase = (size_t)b * NN * KH;     // u64 units
    const size_t obase = (size_t)b * NN * NN;

    // Issue all global loads up front for MLP.
    ull gi[4], gj[4];
    #pragma unroll
    for (int p = 0; p < 4; p++) {
        int idx = tid + 256 * p;
        int nl = idx >> 4, kk = idx & 15;
        gi[p] = G2[gbase + (size_t)(i0 + nl) * KH + kk];
        gj[p] = G2[gbase + (size_t)(j0 + nl) * KH + kk];
    }

    const float alpha = __ldg(alpha_p);
    const float beta  = __ldg(beta_p);

    float bp[4][4];
    #pragma unroll
    for (int ii = 0; ii < 4; ii++) {
        const size_t rb = obase + (size_t)(i0 + ty + 16 * ii) * NN + j0;
        #pragma unroll
        for (int jj = 0; jj < 4; jj++)
            bp[ii][jj] = __ldg(&Bprev[rb + tx + 16 * jj]);
    }

    #pragma unroll
    for (int p = 0; p < 4; p++) {
        int idx = tid + 256 * p;
        int nl = idx >> 4, kk = idx & 15;
        GiT[kk][nl] = gi[p];
        GjT[kk][nl] = gj[p];
    }
    __syncthreads();

    // Row squared-norms from the resident tiles (threads 0..127)
    if (tid < 128) {
        const int nl = tid & 63;
        float s = 0.f;
        if (tid < 64) {
            #pragma unroll
            for (int kk = 0; kk < 16; kk++) {
                float2 v = unpack2(GiT[kk][nl]);
                s += v.x * v.x + v.y * v.y;
            }
            GsqI[nl] = s;
        } else {
            #pragma unroll
            for (int kk = 0; kk < 16; kk++) {
                float2 v = unpack2(GjT[kk][nl]);
                s += v.x * v.x + v.y * v.y;
            }
            GsqJ[nl] = s;
        }
    }
    __syncthreads();

    ull acc[4][4];
    #pragma unroll
    for (int ii = 0; ii < 4; ii++)
        #pragma unroll
        for (int jj = 0; jj < 4; jj++) acc[ii][jj] = 0ULL;

    #pragma unroll
    for (int kk = 0; kk < 16; kk++) {
        ull av[4], bv[4];
        #pragma unroll
        for (int ii = 0; ii < 4; ii++) av[ii] = GiT[kk][ty + 16 * ii];
        #pragma unroll
        for (int jj = 0; jj < 4; jj++) bv[jj] = GjT[kk][tx + 16 * jj];
        #pragma unroll
        for (int ii = 0; ii < 4; ii++)
            #pragma unroll
            for (int jj = 0; jj < 4; jj++)
                acc[ii][jj] = ffma2(av[ii], bv[jj], acc[ii][jj]);
    }

    #pragma unroll
    for (int ii = 0; ii < 4; ii++) {
        const float si = GsqI[ty + 16 * ii];
        const size_t rb = obase + (size_t)(i0 + ty + 16 * ii) * NN + j0;
        #pragma unroll
        for (int jj = 0; jj < 4; jj++) {
            float2 v = unpack2(acc[ii][jj]);
            float dist = si + GsqJ[tx + 16 * jj] - 2.0f * (v.x + v.y);
            dist = fmaxf(dist, 0.0f);
            float o = alpha * bp[ii][jj] - beta * dist;
            o = fminf(fmaxf(o, -CLAMP_V), CLAMP_V);
            Out[rb + tx + 16 * jj] = o;
        }
    }
}

// ============================================================================
extern "C" void kernel_launch(void* const* d_in, const int* in_sizes, int n_in,
                              void* d_out, int out_size) {
    const float* H     = (const float*)d_in[0];   // [4,2048,1024]
    const float* Bprev = (const float*)d_in[1];   // [4,2048,2048]
    const float* W     = (const float*)d_in[2];   // [32,1024]
    const float* alpha = (const float*)d_in[3];   // scalar
    const float* beta  = (const float*)d_in[4];   // scalar
    float* Out = (float*)d_out;

    geom_proj_kernel<<<(NB * NN) / TN1, 256>>>(H, W);
    bias_update_kernel<<<dim3(NN / 64, NN / 64, NB), 256>>>(Bprev, alpha, beta, Out);
}